// round 2
// baseline (speedup 1.0000x reference)
#include <cuda_runtime.h>
#include <cstdint>

// out[b,c,h,w] = image[b,c,h,w] * weight[cam[b],c] + bias[cam[b],c]
// image: [16,3,1024,1024] f32; camera_index: [16] int32 (JAX downcasts int64
// without x64 mode); weight/bias: [34,3] f32.
// Plane size = 1024*1024 floats -> float4-aligned, vectors never cross planes.

static constexpr int PLANE = 1024 * 1024;      // floats per (b,c) plane
static constexpr int TOTAL = 16 * 3 * PLANE;   // 50,331,648 floats
static constexpr int TOTAL4 = TOTAL / 4;       // 12,582,912 float4s

__global__ void colorcal_kernel(const float* __restrict__ image,
                                const int* __restrict__ cam_idx,
                                const float* __restrict__ weight,
                                const float* __restrict__ bias,
                                float* __restrict__ out) {
    int i4 = blockIdx.x * blockDim.x + threadIdx.x;
    if (i4 >= TOTAL4) return;

    int elem = i4 * 4;               // < 2^26, fits int
    int plane = elem >> 20;          // / PLANE
    int c = plane % 3;
    int b = plane / 3;

    int cam = __ldg(&cam_idx[b]);
    float s = __ldg(&weight[cam * 3 + c]);
    float t = __ldg(&bias[cam * 3 + c]);

    float4 v = reinterpret_cast<const float4*>(image)[i4];
    v.x = fmaf(v.x, s, t);
    v.y = fmaf(v.y, s, t);
    v.z = fmaf(v.z, s, t);
    v.w = fmaf(v.w, s, t);
    reinterpret_cast<float4*>(out)[i4] = v;
}

extern "C" void kernel_launch(void* const* d_in, const int* in_sizes, int n_in,
                              void* d_out, int out_size) {
    const float* image = (const float*)d_in[0];
    const int*   cam   = (const int*)d_in[1];
    const float* w     = (const float*)d_in[2];
    const float* bse   = (const float*)d_in[3];
    float*       out   = (float*)d_out;

    constexpr int TPB = 256;
    int blocks = (TOTAL4 + TPB - 1) / TPB;   // 49152
    colorcal_kernel<<<blocks, TPB>>>(image, cam, w, bse, out);
}

// round 3
// speedup vs baseline: 1.0136x; 1.0136x over previous
#include <cuda_runtime.h>
#include <cstdint>

// out[b,c,h,w] = image[b,c,h,w] * weight[cam[b],c] + bias[cam[b],c]
// image: [16,3,1024,1024] f32; camera_index: [16] i32; weight/bias: [34,3] f32.
//
// Layout: TOTAL4 = 12,582,912 float4s. Each block owns a contiguous chunk of
// 256*4 = 1024... no: TPB*VEC = 256*4 = 1024? chunk = TPB*UNROLL = 1024 float4s?
// We use UNROLL=4: chunk = 256*4 = 1024 float4s? -> plane = 262144 float4s,
// 262144 % 1024 == 0, so every block sits inside ONE (b,c) plane: scale/bias
// are uniform per block. 4 independent LDG.128 per thread (MLP_p1=4).

static constexpr int PLANE4  = 262144;            // float4s per (b,c) plane
static constexpr int TOTAL4  = 16 * 3 * PLANE4;   // 12,582,912
static constexpr int TPB     = 256;
static constexpr int UNROLL  = 4;
static constexpr int CHUNK   = TPB * UNROLL;      // 1024 float4s per block
static constexpr int NBLOCKS = TOTAL4 / CHUNK;    // 12288

__global__ void __launch_bounds__(TPB) colorcal_kernel(
        const float4* __restrict__ image,
        const int*    __restrict__ cam_idx,
        const float*  __restrict__ weight,
        const float*  __restrict__ bias,
        float4*       __restrict__ out) {
    int base = blockIdx.x * CHUNK;

    // (b,c) uniform across the block: CHUNK divides PLANE4 exactly.
    int plane = base / PLANE4;        // 0..47
    int c = plane % 3;
    int b = plane / 3;
    int cam = __ldg(&cam_idx[b]);
    float s = __ldg(&weight[cam * 3 + c]);
    float t = __ldg(&bias[cam * 3 + c]);

    int i0 = base + threadIdx.x;

    // Front-batch the 4 independent 16B loads (MLP_p1 = 4).
    float4 v[UNROLL];
#pragma unroll
    for (int k = 0; k < UNROLL; k++)
        v[k] = __ldcs(&image[i0 + k * TPB]);

#pragma unroll
    for (int k = 0; k < UNROLL; k++) {
        float4 r;
        r.x = fmaf(v[k].x, s, t);
        r.y = fmaf(v[k].y, s, t);
        r.z = fmaf(v[k].z, s, t);
        r.w = fmaf(v[k].w, s, t);
        __stcs(&out[i0 + k * TPB], r);
    }
}

extern "C" void kernel_launch(void* const* d_in, const int* in_sizes, int n_in,
                              void* d_out, int out_size) {
    const float4* image = (const float4*)d_in[0];
    const int*    cam   = (const int*)d_in[1];
    const float*  w     = (const float*)d_in[2];
    const float*  bse   = (const float*)d_in[3];
    float4*       out   = (float4*)d_out;

    colorcal_kernel<<<NBLOCKS, TPB>>>(image, cam, w, bse, out);
}